// round 11
// baseline (speedup 1.0000x reference)
#include <cuda_runtime.h>
#include <cuda_fp16.h>
#include <mma.h>

using namespace nvcuda;

#define N_NODES 100000
#define E_MAX   3400000
#define F 128
#define SCAN_NBLK ((N_NODES + 1023) / 1024)   // 98

// ---- static device scratch (allocation-free requirement) ----
__device__ __half    g_h0[N_NODES * F];       // hidden states, fp16
__device__ __half    g_h1[N_NODES * F];
__device__ float     g_g [N_NODES * F];       // fp32 path (layer-4 logits)
__device__ __half    g_g16[N_NODES * F];      // fp16 GEMM output (pre-quant + self term)
__device__ unsigned  g_q8[N_NODES * 32];      // int8 gather payload (4 per uint)
__device__ float     g_qs[N_NODES];           // per-row dequant scale
__device__ float     g_dinv[N_NODES];
__device__ int       g_cnt[N_NODES];
__device__ int       g_pos[N_NODES];
__device__ int       g_rowptr[N_NODES + 1];
__device__ int       g_col[E_MAX];
__device__ int       g_bsum[128];
__device__ int       g_boff[128];

__device__ __forceinline__ __half* pick(int s) { return s == 0 ? g_h0 : g_h1; }

struct alignas(16) Half8 { __half2 a, b, c, d; };

// ---- packed f32x2 FMA helpers (gemm32) ----
__device__ __forceinline__ void ffma2(unsigned long long& d,
                                      unsigned long long a, unsigned long long b) {
    asm("fma.rn.f32x2 %0, %1, %2, %0;" : "+l"(d) : "l"(a), "l"(b));
}
__device__ __forceinline__ unsigned long long pack2(float x, float y) {
    unsigned long long r;
    asm("mov.b64 %0, {%1, %2};" : "=l"(r) : "f"(x), "f"(y));
    return r;
}
__device__ __forceinline__ void unpack2(unsigned long long v, float& x, float& y) {
    unsigned lo, hi;
    asm("mov.b64 {%0, %1}, %2;" : "=r"(lo), "=r"(hi) : "l"(v));
    x = __uint_as_float(lo); y = __uint_as_float(hi);
}

__device__ __forceinline__ Half8 to_h8(float4 a0, float4 a1) {
    Half8 h;
    h.a = __floats2half2_rn(a0.x, a0.y);
    h.b = __floats2half2_rn(a0.z, a0.w);
    h.c = __floats2half2_rn(a1.x, a1.y);
    h.d = __floats2half2_rn(a1.z, a1.w);
    return h;
}

// ---------------- CSR construction ----------------
// edge_index is int32 (JAX default x64-disabled).

__global__ void k_zero() {
    int i = blockIdx.x * blockDim.x + threadIdx.x;
    if (i < N_NODES) { g_cnt[i] = 0; g_pos[i] = 0; }
}

__global__ void k_count(const int* __restrict__ ei, int E) {
    int e = blockIdx.x * blockDim.x + threadIdx.x;
    if (e < E) {
        int d = ei[E + e];
        if ((unsigned)d < N_NODES) atomicAdd(&g_cnt[d], 1);
    }
}

__global__ void k_dinv() {
    int i = blockIdx.x * blockDim.x + threadIdx.x;
    if (i < N_NODES) {
        float deg = (float)(g_cnt[i] + 1);   // +1 self loop
        g_dinv[i] = rsqrtf(deg);
    }
}

__global__ __launch_bounds__(1024) void k_scan1() {
    __shared__ int wsum[32];
    int tid = threadIdx.x, lane = tid & 31, wid = tid >> 5;
    int i = blockIdx.x * 1024 + tid;
    int v = (i < N_NODES) ? g_cnt[i] : 0;
    int x = v;
    #pragma unroll
    for (int off = 1; off < 32; off <<= 1) {
        int t = __shfl_up_sync(0xffffffffu, x, off);
        if (lane >= off) x += t;
    }
    if (lane == 31) wsum[wid] = x;
    __syncthreads();
    if (wid == 0) {
        int w = wsum[lane];
        #pragma unroll
        for (int off = 1; off < 32; off <<= 1) {
            int t = __shfl_up_sync(0xffffffffu, w, off);
            if (lane >= off) w += t;
        }
        wsum[lane] = w;
    }
    __syncthreads();
    int excl = x - v + (wid ? wsum[wid - 1] : 0);
    if (i < N_NODES) g_rowptr[i] = excl;
    if (tid == 0) g_bsum[blockIdx.x] = wsum[31];
}

__global__ __launch_bounds__(128) void k_scan2() {
    __shared__ int s[128];
    int tid = threadIdx.x;
    int v = (tid < SCAN_NBLK) ? g_bsum[tid] : 0;
    s[tid] = v;
    __syncthreads();
    #pragma unroll
    for (int off = 1; off < 128; off <<= 1) {
        int t = (tid >= off) ? s[tid - off] : 0;
        __syncthreads();
        s[tid] += t;
        __syncthreads();
    }
    g_boff[tid] = s[tid] - v;          // exclusive
    if (tid == 127) g_rowptr[N_NODES] = s[127];
}

__global__ __launch_bounds__(1024) void k_scan3() {
    int i = blockIdx.x * 1024 + threadIdx.x;
    if (i < N_NODES) g_rowptr[i] += g_boff[blockIdx.x];
}

__global__ void k_fill(const int* __restrict__ ei, int E) {
    int e = blockIdx.x * blockDim.x + threadIdx.x;
    if (e < E) {
        int s = ei[e];
        int d = ei[E + e];
        if ((unsigned)s < N_NODES && (unsigned)d < N_NODES) {
            int p = atomicAdd(&g_pos[d], 1);
            g_col[g_rowptr[d] + p] = s;
        }
    }
}

// ---------------- GEMM (tensor cores): g_g16 = half((A @ W) * dinv) ----------------
// __half WMMA m16n16k16, fp32 accumulate. 21 KB smem, 2 blk/SM.

__global__ __launch_bounds__(256) void k_gemm128(const float* __restrict__ Aext,
                                                 int srcsel,
                                                 const float* __restrict__ W, int M) {
    const __half* __restrict__ Ah = (srcsel < 0) ? nullptr : pick(srcsel);
    __shared__ __half As[128][24];    // ld = 24 elems (48B)
    __shared__ __half Bs[16][136];    // ld = 136 elems (272B)
    __shared__ float  Cs[8][16 * 20]; // epilogue staging, ld = 20 floats

    int tid  = threadIdx.x;
    int wid  = tid >> 5;
    int lane = tid & 31;
    int row0 = blockIdx.x * 128;
    int wr = wid >> 1;
    int wc = wid & 1;

    wmma::fragment<wmma::accumulator, 16, 16, 16, float> c[2][4];
    #pragma unroll
    for (int i = 0; i < 2; i++)
        #pragma unroll
        for (int j = 0; j < 4; j++) wmma::fill_fragment(c[i][j], 0.f);

    int ar   = tid >> 1;
    int acst = (tid & 1) * 8;
    int agrow = row0 + ar;
    bool avalid = agrow < M;

    for (int k0 = 0; k0 < 128; k0 += 16) {
        {
            Half8 h;
            if (srcsel < 0) {
                float4 a0, a1;
                if (avalid) {
                    a0 = *(const float4*)&Aext[(long long)agrow * 128 + k0 + acst];
                    a1 = *(const float4*)&Aext[(long long)agrow * 128 + k0 + acst + 4];
                } else {
                    a0 = make_float4(0.f, 0.f, 0.f, 0.f); a1 = a0;
                }
                h = to_h8(a0, a1);
            } else {
                if (avalid)
                    h = *(const Half8*)&Ah[(long long)agrow * 128 + k0 + acst];
                else
                    h.a = h.b = h.c = h.d = __half2half2(__float2half(0.f));
            }
            *(Half8*)&As[ar][acst] = h;
        }
        {
            int r2 = tid >> 4;
            int c2 = (tid & 15) * 8;
            float4 b0 = *(const float4*)&W[(k0 + r2) * 128 + c2];
            float4 b1 = *(const float4*)&W[(k0 + r2) * 128 + c2 + 4];
            *(Half8*)&Bs[r2][c2] = to_h8(b0, b1);
        }
        __syncthreads();

        wmma::fragment<wmma::matrix_a, 16, 16, 16, __half, wmma::row_major> af[2];
        wmma::fragment<wmma::matrix_b, 16, 16, 16, __half, wmma::row_major> bf[4];
        #pragma unroll
        for (int i = 0; i < 2; i++)
            wmma::load_matrix_sync(af[i], &As[wr * 32 + i * 16][0], 24);
        #pragma unroll
        for (int j = 0; j < 4; j++)
            wmma::load_matrix_sync(bf[j], &Bs[0][wc * 64 + j * 16], 136);
        #pragma unroll
        for (int i = 0; i < 2; i++)
            #pragma unroll
            for (int j = 0; j < 4; j++)
                wmma::mma_sync(c[i][j], af[i], bf[j], c[i][j]);
        __syncthreads();
    }

    #pragma unroll
    for (int i = 0; i < 2; i++) {
        #pragma unroll
        for (int j = 0; j < 4; j++) {
            wmma::store_matrix_sync(&Cs[wid][0], c[i][j], 20, wmma::mem_row_major);
            __syncwarp();
            int rr = lane >> 1;
            int c0 = (lane & 1) * 8;
            int grow = row0 + wr * 32 + i * 16 + rr;
            if (grow < M) {
                float d = g_dinv[grow];
                const float* src = &Cs[wid][rr * 20 + c0];
                Half8 h;
                h.a = __floats2half2_rn(src[0] * d, src[1] * d);
                h.b = __floats2half2_rn(src[2] * d, src[3] * d);
                h.c = __floats2half2_rn(src[4] * d, src[5] * d);
                h.d = __floats2half2_rn(src[6] * d, src[7] * d);
                *(Half8*)&g_g16[(long long)grow * 128 + wc * 64 + j * 16 + c0] = h;
            }
            __syncwarp();
        }
    }
}

// ---------------- Quantize: g_g16 row -> int8 row + per-row scale ----------------
// warp per row: 8B/lane read, warp max-reduce, 4B/lane write.

__global__ __launch_bounds__(256) void k_quant() {
    int wid = threadIdx.x >> 5, lane = threadIdx.x & 31;
    int row = blockIdx.x * 8 + wid;
    if (row >= N_NODES) return;
    uint2 v = ((const uint2*)g_g16)[(long long)row * 32 + lane];
    float2 a = __half22float2(*(__half2*)&v.x);
    float2 b = __half22float2(*(__half2*)&v.y);
    float m = fmaxf(fmaxf(fabsf(a.x), fabsf(a.y)), fmaxf(fabsf(b.x), fabsf(b.y)));
    #pragma unroll
    for (int off = 16; off; off >>= 1)
        m = fmaxf(m, __shfl_xor_sync(0xffffffffu, m, off));
    float inv = (m > 0.f) ? 127.f / m : 0.f;
    int q0 = __float2int_rn(a.x * inv);
    int q1 = __float2int_rn(a.y * inv);
    int q2 = __float2int_rn(b.x * inv);
    int q3 = __float2int_rn(b.y * inv);
    unsigned q = (q0 & 0xff) | ((q1 & 0xff) << 8) | ((q2 & 0xff) << 16) | (q3 << 24);
    g_q8[(long long)row * 32 + lane] = q;
    if (lane == 0) g_qs[row] = (m > 0.f) ? m / 127.f : 0.f;
}

// ---------------- GEMM 128x32 (last layer), fp16 A -> fp32 FFMA2 -> g_g [M,32] ----

__global__ __launch_bounds__(256) void k_gemm32(int srcsel,
                                                const float* __restrict__ W, int M) {
    const __half* __restrict__ A = pick(srcsel);
    __shared__ float As[16][128];
    __shared__ float Bs[16][32];
    int tid = threadIdx.x;
    int row0 = blockIdx.x * 128;
    int tr = tid >> 3;
    int tc = tid & 7;
    unsigned long long acc[2][4];
    #pragma unroll
    for (int p = 0; p < 2; p++)
        #pragma unroll
        for (int j = 0; j < 4; j++) acc[p][j] = 0ull;

    for (int k0 = 0; k0 < 128; k0 += 16) {
        #pragma unroll
        for (int it = 0; it < 2; it++) {
            int idx = tid + it * 256;
            int r  = idx >> 2;
            int kc = (idx & 3) * 4;
            int grow = row0 + r;
            float4 a;
            if (grow < M) {
                uint2 hv = *(const uint2*)&A[(long long)grow * 128 + k0 + kc];
                float2 p0 = __half22float2(*(__half2*)&hv.x);
                float2 p1 = __half22float2(*(__half2*)&hv.y);
                a = make_float4(p0.x, p0.y, p1.x, p1.y);
            } else {
                a = make_float4(0.f, 0.f, 0.f, 0.f);
            }
            As[kc + 0][r] = a.x; As[kc + 1][r] = a.y;
            As[kc + 2][r] = a.z; As[kc + 3][r] = a.w;
        }
        if (tid < 128) {
            int r = tid >> 3;
            int c = (tid & 7) * 4;
            *(float4*)&Bs[r][c] = *(const float4*)&W[(k0 + r) * 32 + c];
        }
        __syncthreads();
        #pragma unroll
        for (int k = 0; k < 16; k++) {
            const unsigned long long* ap =
                (const unsigned long long*)&As[k][tr * 4];
            unsigned long long a01 = ap[0], a23 = ap[1];
            float b0[4];
            *(float4*)&b0[0] = *(const float4*)&Bs[k][tc * 4];
            #pragma unroll
            for (int j = 0; j < 4; j++) {
                unsigned long long bb = pack2(b0[j], b0[j]);
                ffma2(acc[0][j], a01, bb);
                ffma2(acc[1][j], a23, bb);
            }
        }
        __syncthreads();
    }
    #pragma unroll
    for (int p = 0; p < 2; p++) {
        float lo[4], hi[4];
        #pragma unroll
        for (int j = 0; j < 4; j++) unpack2(acc[p][j], lo[j], hi[j]);
        int r0 = row0 + tr * 4 + 2 * p;
        if (r0 < M) {
            float d = g_dinv[r0];
            float4 o = make_float4(lo[0] * d, lo[1] * d, lo[2] * d, lo[3] * d);
            *(float4*)&g_g[(long long)r0 * 32 + tc * 4] = o;
        }
        if (r0 + 1 < M) {
            float d = g_dinv[r0 + 1];
            float4 o = make_float4(hi[0] * d, hi[1] * d, hi[2] * d, hi[3] * d);
            *(float4*)&g_g[(long long)(r0 + 1) * 32 + tc * 4] = o;
        }
    }
}

// ---------------- Aggregation (128-wide, int8 payload + per-row scale) ------------
// warp per node; indices AND scales staged in smem; LDGs (4B int8x4) batched x8.
// Self-loop term read from fp16 (exact); neighbor terms dequantized.

__global__ __launch_bounds__(256) void k_agg128(const float* __restrict__ bias,
                                                int dstsel) {
    __shared__ int   sidx[8][32];
    __shared__ float sscl[8][32];
    __half* __restrict__ out = pick(dstsel);
    int wid = threadIdx.x >> 5, lane = threadIdx.x & 31;
    int gw = blockIdx.x * 8 + wid;
    if (gw >= N_NODES) return;

    uint2 self = ((const uint2*)g_g16)[(long long)gw * 32 + lane];
    float2 f0 = __half22float2(*(__half2*)&self.x);
    float2 f1 = __half22float2(*(__half2*)&self.y);
    float4 acc = make_float4(f0.x, f0.y, f1.x, f1.y);

    int s0 = g_rowptr[gw], s1 = g_rowptr[gw + 1];
    for (int base = s0; base < s1; base += 32) {
        int n = min(32, s1 - base);
        int idx = (base + lane < s1) ? g_col[base + lane] : 0;
        sidx[wid][lane] = idx;
        sscl[wid][lane] = (base + lane < s1) ? g_qs[idx] : 0.f;
        __syncwarp();
        int j = 0;
        for (; j + 8 <= n; j += 8) {
            unsigned v[8]; float sc[8];
            #pragma unroll
            for (int t = 0; t < 8; t++) {
                int s = sidx[wid][j + t];
                v[t]  = __ldg(&g_q8[(long long)s * 32 + lane]);
                sc[t] = sscl[wid][j + t];
            }
            #pragma unroll
            for (int t = 0; t < 8; t++) {
                char4 c = *(char4*)&v[t];
                acc.x += sc[t] * (float)c.x;
                acc.y += sc[t] * (float)c.y;
                acc.z += sc[t] * (float)c.z;
                acc.w += sc[t] * (float)c.w;
            }
        }
        for (; j < n; j++) {
            int s = sidx[wid][j];
            unsigned v = __ldg(&g_q8[(long long)s * 32 + lane]);
            float sc = sscl[wid][j];
            char4 c = *(char4*)&v;
            acc.x += sc * (float)c.x;
            acc.y += sc * (float)c.y;
            acc.z += sc * (float)c.z;
            acc.w += sc * (float)c.w;
        }
        __syncwarp();
    }
    float d = g_dinv[gw];
    float4 b = ((const float4*)bias)[lane];
    float rx = fmaxf(d * acc.x + b.x, 0.f);
    float ry = fmaxf(d * acc.y + b.y, 0.f);
    float rz = fmaxf(d * acc.z + b.z, 0.f);
    float rw = fmaxf(d * acc.w + b.w, 0.f);
    uint2 o;
    *(__half2*)&o.x = __floats2half2_rn(rx, ry);
    *(__half2*)&o.y = __floats2half2_rn(rz, rw);
    ((uint2*)out)[(long long)gw * 32 + lane] = o;
}

// ---------------- Aggregation (32-wide, fp32) + log_softmax fused ----------------

__global__ __launch_bounds__(256) void k_agg32_lsm(const float* __restrict__ bias,
                                                   float* __restrict__ out) {
    __shared__ int sidx[8][32];
    int wid = threadIdx.x >> 5, lane = threadIdx.x & 31;
    int gw = blockIdx.x * 8 + wid;
    if (gw >= N_NODES) return;
    float acc = g_g[(long long)gw * 32 + lane];
    int s0 = g_rowptr[gw], s1 = g_rowptr[gw + 1];
    for (int base = s0; base < s1; base += 32) {
        int n = min(32, s1 - base);
        sidx[wid][lane] = (base + lane < s1) ? g_col[base + lane] : 0;
        __syncwarp();
        int j = 0;
        for (; j + 8 <= n; j += 8) {
            float v[8];
            #pragma unroll
            for (int t = 0; t < 8; t++) {
                int s = sidx[wid][j + t];
                v[t] = __ldg(&g_g[(long long)s * 32 + lane]);
            }
            #pragma unroll
            for (int t = 0; t < 8; t++) acc += v[t];
        }
        for (; j < n; j++) {
            int s = sidx[wid][j];
            acc += __ldg(&g_g[(long long)s * 32 + lane]);
        }
        __syncwarp();
    }
    float v = g_dinv[gw] * acc + bias[lane];
    float mx = v;
    #pragma unroll
    for (int off = 16; off; off >>= 1)
        mx = fmaxf(mx, __shfl_xor_sync(0xffffffffu, mx, off));
    float e = expf(v - mx);
    float sum = e;
    #pragma unroll
    for (int off = 16; off; off >>= 1)
        sum += __shfl_xor_sync(0xffffffffu, sum, off);
    out[(long long)gw * 32 + lane] = v - mx - logf(sum);
}

// ---------------- launch ----------------

extern "C" void kernel_launch(void* const* d_in, const int* in_sizes, int n_in,
                              void* d_out, int out_size) {
    const float* x  = (const float*)d_in[0];
    const int*   ei = (const int*)d_in[1];       // int32
    const float* W1 = (const float*)d_in[2]; const float* b1 = (const float*)d_in[3];
    const float* W2 = (const float*)d_in[4]; const float* b2 = (const float*)d_in[5];
    const float* W3 = (const float*)d_in[6]; const float* b3 = (const float*)d_in[7];
    const float* W4 = (const float*)d_in[8]; const float* b4 = (const float*)d_in[9];
    float* out = (float*)d_out;
    int E = in_sizes[1] / 2;
    if (E > E_MAX) E = E_MAX;

    const int TB = 256;
    int gN = (N_NODES + TB - 1) / TB;
    int gE = (E + TB - 1) / TB;
    int gGemm = (N_NODES + 127) / 128;
    int gAgg  = (N_NODES + 7) / 8;

    // CSR build + layer-1 GEMM (4th launch -> ncu capture slot)
    k_zero   <<<gN, TB>>>();
    k_count  <<<gE, TB>>>(ei, E);
    k_dinv   <<<gN, TB>>>();
    k_gemm128<<<gGemm, TB>>>(x, -1, W1, N_NODES);
    k_scan1  <<<SCAN_NBLK, 1024>>>();
    k_scan2  <<<1, 128>>>();
    k_scan3  <<<SCAN_NBLK, 1024>>>();
    k_fill   <<<gE, TB>>>(ei, E);

    // layer 1
    k_quant  <<<gAgg, TB>>>();
    k_agg128 <<<gAgg, TB>>>(b1, 0);
    // layer 2
    k_gemm128<<<gGemm, TB>>>(nullptr, 0, W2, N_NODES);
    k_quant  <<<gAgg, TB>>>();
    k_agg128 <<<gAgg, TB>>>(b2, 1);
    // layer 3
    k_gemm128<<<gGemm, TB>>>(nullptr, 1, W3, N_NODES);
    k_quant  <<<gAgg, TB>>>();
    k_agg128 <<<gAgg, TB>>>(b3, 0);
    // layer 4 (transform first -> 32-wide aggregation, fp32) + log_softmax
    k_gemm32 <<<gGemm, TB>>>(0, W4, N_NODES);
    k_agg32_lsm<<<gAgg, TB>>>(b4, out);
}

// round 12
// speedup vs baseline: 1.2077x; 1.2077x over previous
#include <cuda_runtime.h>
#include <cuda_fp16.h>
#include <mma.h>

using namespace nvcuda;

#define N_NODES 100000
#define E_MAX   3400000
#define F 128
#define SCAN_NBLK ((N_NODES + 1023) / 1024)   // 98

// ---- static device scratch (allocation-free requirement) ----
__device__ __half g_h0[N_NODES * F];          // hidden states, fp16
__device__ __half g_h1[N_NODES * F];
__device__ float  g_g [N_NODES * F];          // fp32 path (layer-4 logits)
__device__ __half g_g16[N_NODES * F];         // fp16 gather payload (layers 1-3)
__device__ float  g_dinv[N_NODES];
__device__ int    g_cnt[N_NODES];
__device__ int    g_pos[N_NODES];
__device__ int    g_rowptr[N_NODES + 1];
__device__ int    g_col[E_MAX];
__device__ int    g_bsum[128];
__device__ int    g_boff[128];

__device__ __forceinline__ __half* pick(int s) { return s == 0 ? g_h0 : g_h1; }

struct alignas(16) Half8 { __half2 a, b, c, d; };

// ---- packed f32x2 FMA helpers (gemm32) ----
__device__ __forceinline__ void ffma2(unsigned long long& d,
                                      unsigned long long a, unsigned long long b) {
    asm("fma.rn.f32x2 %0, %1, %2, %0;" : "+l"(d) : "l"(a), "l"(b));
}
__device__ __forceinline__ unsigned long long pack2(float x, float y) {
    unsigned long long r;
    asm("mov.b64 %0, {%1, %2};" : "=l"(r) : "f"(x), "f"(y));
    return r;
}
__device__ __forceinline__ void unpack2(unsigned long long v, float& x, float& y) {
    unsigned lo, hi;
    asm("mov.b64 {%0, %1}, %2;" : "=r"(lo), "=r"(hi) : "l"(v));
    x = __uint_as_float(lo); y = __uint_as_float(hi);
}

__device__ __forceinline__ Half8 to_h8(float4 a0, float4 a1) {
    Half8 h;
    h.a = __floats2half2_rn(a0.x, a0.y);
    h.b = __floats2half2_rn(a0.z, a0.w);
    h.c = __floats2half2_rn(a1.x, a1.y);
    h.d = __floats2half2_rn(a1.z, a1.w);
    return h;
}

// ---------------- CSR construction ----------------
// edge_index is int32 (JAX default x64-disabled).

__global__ void k_zero() {
    int i = blockIdx.x * blockDim.x + threadIdx.x;
    if (i < N_NODES) { g_cnt[i] = 0; g_pos[i] = 0; }
}

__global__ void k_count(const int* __restrict__ ei, int E) {
    int e = blockIdx.x * blockDim.x + threadIdx.x;
    if (e < E) {
        int d = ei[E + e];
        if ((unsigned)d < N_NODES) atomicAdd(&g_cnt[d], 1);
    }
}

__global__ void k_dinv() {
    int i = blockIdx.x * blockDim.x + threadIdx.x;
    if (i < N_NODES) {
        float deg = (float)(g_cnt[i] + 1);   // +1 self loop
        g_dinv[i] = rsqrtf(deg);
    }
}

__global__ __launch_bounds__(1024) void k_scan1() {
    __shared__ int wsum[32];
    int tid = threadIdx.x, lane = tid & 31, wid = tid >> 5;
    int i = blockIdx.x * 1024 + tid;
    int v = (i < N_NODES) ? g_cnt[i] : 0;
    int x = v;
    #pragma unroll
    for (int off = 1; off < 32; off <<= 1) {
        int t = __shfl_up_sync(0xffffffffu, x, off);
        if (lane >= off) x += t;
    }
    if (lane == 31) wsum[wid] = x;
    __syncthreads();
    if (wid == 0) {
        int w = wsum[lane];
        #pragma unroll
        for (int off = 1; off < 32; off <<= 1) {
            int t = __shfl_up_sync(0xffffffffu, w, off);
            if (lane >= off) w += t;
        }
        wsum[lane] = w;
    }
    __syncthreads();
    int excl = x - v + (wid ? wsum[wid - 1] : 0);
    if (i < N_NODES) g_rowptr[i] = excl;
    if (tid == 0) g_bsum[blockIdx.x] = wsum[31];
}

__global__ __launch_bounds__(128) void k_scan2() {
    __shared__ int s[128];
    int tid = threadIdx.x;
    int v = (tid < SCAN_NBLK) ? g_bsum[tid] : 0;
    s[tid] = v;
    __syncthreads();
    #pragma unroll
    for (int off = 1; off < 128; off <<= 1) {
        int t = (tid >= off) ? s[tid - off] : 0;
        __syncthreads();
        s[tid] += t;
        __syncthreads();
    }
    g_boff[tid] = s[tid] - v;          // exclusive
    if (tid == 127) g_rowptr[N_NODES] = s[127];
}

__global__ __launch_bounds__(1024) void k_scan3() {
    int i = blockIdx.x * 1024 + threadIdx.x;
    if (i < N_NODES) g_rowptr[i] += g_boff[blockIdx.x];
}

__global__ void k_fill(const int* __restrict__ ei, int E) {
    int e = blockIdx.x * blockDim.x + threadIdx.x;
    if (e < E) {
        int s = ei[e];
        int d = ei[E + e];
        if ((unsigned)s < N_NODES && (unsigned)d < N_NODES) {
            int p = atomicAdd(&g_pos[d], 1);
            g_col[g_rowptr[d] + p] = s;
        }
    }
}

// ---------------- GEMM (tensor cores): g_g16 = half((A @ W) * dinv) ----------------
// __half WMMA m16n16k16, fp32 accumulate. 21 KB smem, 2 blk/SM. (R10 structure)

__global__ __launch_bounds__(256) void k_gemm128(const float* __restrict__ Aext,
                                                 int srcsel,
                                                 const float* __restrict__ W, int M) {
    const __half* __restrict__ Ah = (srcsel < 0) ? nullptr : pick(srcsel);
    __shared__ __half As[128][24];    // ld = 24 elems (48B)
    __shared__ __half Bs[16][136];    // ld = 136 elems (272B)
    __shared__ float  Cs[8][16 * 20]; // epilogue staging, ld = 20 floats

    int tid  = threadIdx.x;
    int wid  = tid >> 5;
    int lane = tid & 31;
    int row0 = blockIdx.x * 128;
    int wr = wid >> 1;
    int wc = wid & 1;

    wmma::fragment<wmma::accumulator, 16, 16, 16, float> c[2][4];
    #pragma unroll
    for (int i = 0; i < 2; i++)
        #pragma unroll
        for (int j = 0; j < 4; j++) wmma::fill_fragment(c[i][j], 0.f);

    int ar   = tid >> 1;
    int acst = (tid & 1) * 8;
    int agrow = row0 + ar;
    bool avalid = agrow < M;

    for (int k0 = 0; k0 < 128; k0 += 16) {
        {
            Half8 h;
            if (srcsel < 0) {
                float4 a0, a1;
                if (avalid) {
                    a0 = *(const float4*)&Aext[(long long)agrow * 128 + k0 + acst];
                    a1 = *(const float4*)&Aext[(long long)agrow * 128 + k0 + acst + 4];
                } else {
                    a0 = make_float4(0.f, 0.f, 0.f, 0.f); a1 = a0;
                }
                h = to_h8(a0, a1);
            } else {
                if (avalid)
                    h = *(const Half8*)&Ah[(long long)agrow * 128 + k0 + acst];
                else
                    h.a = h.b = h.c = h.d = __half2half2(__float2half(0.f));
            }
            *(Half8*)&As[ar][acst] = h;
        }
        {
            int r2 = tid >> 4;
            int c2 = (tid & 15) * 8;
            float4 b0 = *(const float4*)&W[(k0 + r2) * 128 + c2];
            float4 b1 = *(const float4*)&W[(k0 + r2) * 128 + c2 + 4];
            *(Half8*)&Bs[r2][c2] = to_h8(b0, b1);
        }
        __syncthreads();

        wmma::fragment<wmma::matrix_a, 16, 16, 16, __half, wmma::row_major> af[2];
        wmma::fragment<wmma::matrix_b, 16, 16, 16, __half, wmma::row_major> bf[4];
        #pragma unroll
        for (int i = 0; i < 2; i++)
            wmma::load_matrix_sync(af[i], &As[wr * 32 + i * 16][0], 24);
        #pragma unroll
        for (int j = 0; j < 4; j++)
            wmma::load_matrix_sync(bf[j], &Bs[0][wc * 64 + j * 16], 136);
        #pragma unroll
        for (int i = 0; i < 2; i++)
            #pragma unroll
            for (int j = 0; j < 4; j++)
                wmma::mma_sync(c[i][j], af[i], bf[j], c[i][j]);
        __syncthreads();
    }

    #pragma unroll
    for (int i = 0; i < 2; i++) {
        #pragma unroll
        for (int j = 0; j < 4; j++) {
            wmma::store_matrix_sync(&Cs[wid][0], c[i][j], 20, wmma::mem_row_major);
            __syncwarp();
            int rr = lane >> 1;
            int c0 = (lane & 1) * 8;
            int grow = row0 + wr * 32 + i * 16 + rr;
            if (grow < M) {
                float d = g_dinv[grow];
                const float* src = &Cs[wid][rr * 20 + c0];
                Half8 h;
                h.a = __floats2half2_rn(src[0] * d, src[1] * d);
                h.b = __floats2half2_rn(src[2] * d, src[3] * d);
                h.c = __floats2half2_rn(src[4] * d, src[5] * d);
                h.d = __floats2half2_rn(src[6] * d, src[7] * d);
                *(Half8*)&g_g16[(long long)grow * 128 + wc * 64 + j * 16 + c0] = h;
            }
            __syncwarp();
        }
    }
}

// ---------------- GEMM 128x32 (last layer), fp16 A -> fp32 FFMA2 -> g_g [M,32] ----

__global__ __launch_bounds__(256) void k_gemm32(int srcsel,
                                                const float* __restrict__ W, int M) {
    const __half* __restrict__ A = pick(srcsel);
    __shared__ float As[16][128];
    __shared__ float Bs[16][32];
    int tid = threadIdx.x;
    int row0 = blockIdx.x * 128;
    int tr = tid >> 3;
    int tc = tid & 7;
    unsigned long long acc[2][4];
    #pragma unroll
    for (int p = 0; p < 2; p++)
        #pragma unroll
        for (int j = 0; j < 4; j++) acc[p][j] = 0ull;

    for (int k0 = 0; k0 < 128; k0 += 16) {
        #pragma unroll
        for (int it = 0; it < 2; it++) {
            int idx = tid + it * 256;
            int r  = idx >> 2;
            int kc = (idx & 3) * 4;
            int grow = row0 + r;
            float4 a;
            if (grow < M) {
                uint2 hv = *(const uint2*)&A[(long long)grow * 128 + k0 + kc];
                float2 p0 = __half22float2(*(__half2*)&hv.x);
                float2 p1 = __half22float2(*(__half2*)&hv.y);
                a = make_float4(p0.x, p0.y, p1.x, p1.y);
            } else {
                a = make_float4(0.f, 0.f, 0.f, 0.f);
            }
            As[kc + 0][r] = a.x; As[kc + 1][r] = a.y;
            As[kc + 2][r] = a.z; As[kc + 3][r] = a.w;
        }
        if (tid < 128) {
            int r = tid >> 3;
            int c = (tid & 7) * 4;
            *(float4*)&Bs[r][c] = *(const float4*)&W[(k0 + r) * 32 + c];
        }
        __syncthreads();
        #pragma unroll
        for (int k = 0; k < 16; k++) {
            const unsigned long long* ap =
                (const unsigned long long*)&As[k][tr * 4];
            unsigned long long a01 = ap[0], a23 = ap[1];
            float b0[4];
            *(float4*)&b0[0] = *(const float4*)&Bs[k][tc * 4];
            #pragma unroll
            for (int j = 0; j < 4; j++) {
                unsigned long long bb = pack2(b0[j], b0[j]);
                ffma2(acc[0][j], a01, bb);
                ffma2(acc[1][j], a23, bb);
            }
        }
        __syncthreads();
    }
    #pragma unroll
    for (int p = 0; p < 2; p++) {
        float lo[4], hi[4];
        #pragma unroll
        for (int j = 0; j < 4; j++) unpack2(acc[p][j], lo[j], hi[j]);
        int r0 = row0 + tr * 4 + 2 * p;
        if (r0 < M) {
            float d = g_dinv[r0];
            float4 o = make_float4(lo[0] * d, lo[1] * d, lo[2] * d, lo[3] * d);
            *(float4*)&g_g[(long long)r0 * 32 + tc * 4] = o;
        }
        if (r0 + 1 < M) {
            float d = g_dinv[r0 + 1];
            float4 o = make_float4(hi[0] * d, hi[1] * d, hi[2] * d, hi[3] * d);
            *(float4*)&g_g[(long long)(r0 + 1) * 32 + tc * 4] = o;
        }
    }
}

// ---------------- Aggregation (128-wide, fp16, HALF-WARP per node) ---------------
// 16 lanes/node, 16B (8 fp16) per lane. Indices broadcast via width-16 shuffles
// with per-half masks (divergence-safe). Payload LDGs batched x8.

__global__ __launch_bounds__(256) void k_agg128(const float* __restrict__ bias,
                                                int dstsel) {
    __half* __restrict__ out = pick(dstsel);
    int tid  = threadIdx.x;
    int wid  = tid >> 5;
    int lane = tid & 31;
    int half = lane >> 4;              // 0 or 1
    int sub  = lane & 15;              // lane within half-warp
    unsigned hmask = 0xFFFFu << (half * 16);
    int gw = blockIdx.x * 16 + wid * 2 + half;
    if (gw >= N_NODES) return;

    const uint4* __restrict__ gg = (const uint4*)g_g16;   // 16B = 8 fp16 per elem

    uint4 self = gg[(long long)gw * 16 + sub];
    float2 a0 = __half22float2(*(__half2*)&self.x);
    float2 a1 = __half22float2(*(__half2*)&self.y);
    float2 a2 = __half22float2(*(__half2*)&self.z);
    float2 a3 = __half22float2(*(__half2*)&self.w);

    int s0 = g_rowptr[gw], s1 = g_rowptr[gw + 1];
    for (int base = s0; base < s1; base += 16) {
        int n = min(16, s1 - base);
        int idx = (base + sub < s1) ? g_col[base + sub] : 0;
        int j = 0;
        for (; j + 8 <= n; j += 8) {
            uint4 v[8];
            #pragma unroll
            for (int t = 0; t < 8; t++) {
                int s = __shfl_sync(hmask, idx, j + t, 16);
                v[t] = __ldg(&gg[(long long)s * 16 + sub]);
            }
            #pragma unroll
            for (int t = 0; t < 8; t++) {
                float2 b0 = __half22float2(*(__half2*)&v[t].x);
                float2 b1 = __half22float2(*(__half2*)&v[t].y);
                float2 b2 = __half22float2(*(__half2*)&v[t].z);
                float2 b3 = __half22float2(*(__half2*)&v[t].w);
                a0.x += b0.x; a0.y += b0.y;
                a1.x += b1.x; a1.y += b1.y;
                a2.x += b2.x; a2.y += b2.y;
                a3.x += b3.x; a3.y += b3.y;
            }
        }
        for (; j < n; j++) {
            int s = __shfl_sync(hmask, idx, j, 16);
            uint4 v = __ldg(&gg[(long long)s * 16 + sub]);
            float2 b0 = __half22float2(*(__half2*)&v.x);
            float2 b1 = __half22float2(*(__half2*)&v.y);
            float2 b2 = __half22float2(*(__half2*)&v.z);
            float2 b3 = __half22float2(*(__half2*)&v.w);
            a0.x += b0.x; a0.y += b0.y;
            a1.x += b1.x; a1.y += b1.y;
            a2.x += b2.x; a2.y += b2.y;
            a3.x += b3.x; a3.y += b3.y;
        }
    }
    float d = g_dinv[gw];
    float4 bA = ((const float4*)bias)[sub * 2];
    float4 bB = ((const float4*)bias)[sub * 2 + 1];
    float r0 = fmaxf(d * a0.x + bA.x, 0.f);
    float r1 = fmaxf(d * a0.y + bA.y, 0.f);
    float r2 = fmaxf(d * a1.x + bA.z, 0.f);
    float r3 = fmaxf(d * a1.y + bA.w, 0.f);
    float r4 = fmaxf(d * a2.x + bB.x, 0.f);
    float r5 = fmaxf(d * a2.y + bB.y, 0.f);
    float r6 = fmaxf(d * a3.x + bB.z, 0.f);
    float r7 = fmaxf(d * a3.y + bB.w, 0.f);
    uint4 o;
    *(__half2*)&o.x = __floats2half2_rn(r0, r1);
    *(__half2*)&o.y = __floats2half2_rn(r2, r3);
    *(__half2*)&o.z = __floats2half2_rn(r4, r5);
    *(__half2*)&o.w = __floats2half2_rn(r6, r7);
    ((uint4*)out)[(long long)gw * 16 + sub] = o;
}

// ---------------- Aggregation (32-wide, fp32) + log_softmax fused ----------------

__global__ __launch_bounds__(256) void k_agg32_lsm(const float* __restrict__ bias,
                                                   float* __restrict__ out) {
    __shared__ int sidx[8][32];
    int wid = threadIdx.x >> 5, lane = threadIdx.x & 31;
    int gw = blockIdx.x * 8 + wid;
    if (gw >= N_NODES) return;
    float acc = g_g[(long long)gw * 32 + lane];
    int s0 = g_rowptr[gw], s1 = g_rowptr[gw + 1];
    for (int base = s0; base < s1; base += 32) {
        int n = min(32, s1 - base);
        sidx[wid][lane] = (base + lane < s1) ? g_col[base + lane] : 0;
        __syncwarp();
        int j = 0;
        for (; j + 8 <= n; j += 8) {
            float v[8];
            #pragma unroll
            for (int t = 0; t < 8; t++) {
                int s = sidx[wid][j + t];
                v[t] = __ldg(&g_g[(long long)s * 32 + lane]);
            }
            #pragma unroll
            for (int t = 0; t < 8; t++) acc += v[t];
        }
        for (; j < n; j++) {
            int s = sidx[wid][j];
            acc += __ldg(&g_g[(long long)s * 32 + lane]);
        }
        __syncwarp();
    }
    float v = g_dinv[gw] * acc + bias[lane];
    float mx = v;
    #pragma unroll
    for (int off = 16; off; off >>= 1)
        mx = fmaxf(mx, __shfl_xor_sync(0xffffffffu, mx, off));
    float e = expf(v - mx);
    float sum = e;
    #pragma unroll
    for (int off = 16; off; off >>= 1)
        sum += __shfl_xor_sync(0xffffffffu, sum, off);
    out[(long long)gw * 32 + lane] = v - mx - logf(sum);
}

// ---------------- launch ----------------

extern "C" void kernel_launch(void* const* d_in, const int* in_sizes, int n_in,
                              void* d_out, int out_size) {
    const float* x  = (const float*)d_in[0];
    const int*   ei = (const int*)d_in[1];       // int32
    const float* W1 = (const float*)d_in[2]; const float* b1 = (const float*)d_in[3];
    const float* W2 = (const float*)d_in[4]; const float* b2 = (const float*)d_in[5];
    const float* W3 = (const float*)d_in[6]; const float* b3 = (const float*)d_in[7];
    const float* W4 = (const float*)d_in[8]; const float* b4 = (const float*)d_in[9];
    float* out = (float*)d_out;
    int E = in_sizes[1] / 2;
    if (E > E_MAX) E = E_MAX;

    const int TB = 256;
    int gN = (N_NODES + TB - 1) / TB;
    int gE = (E + TB - 1) / TB;
    int gGemm = (N_NODES + 127) / 128;
    int gAgg  = (N_NODES + 7) / 8;        // k_agg32_lsm: 8 nodes/block
    int gAggH = (N_NODES + 15) / 16;      // k_agg128: 16 nodes/block

    // CSR build + layer-1 GEMM (4th launch -> ncu capture slot)
    k_zero   <<<gN, TB>>>();
    k_count  <<<gE, TB>>>(ei, E);
    k_dinv   <<<gN, TB>>>();
    k_gemm128<<<gGemm, TB>>>(x, -1, W1, N_NODES);
    k_scan1  <<<SCAN_NBLK, 1024>>>();
    k_scan2  <<<1, 128>>>();
    k_scan3  <<<SCAN_NBLK, 1024>>>();
    k_fill   <<<gE, TB>>>(ei, E);

    // layer 1
    k_agg128 <<<gAggH, TB>>>(b1, 0);
    // layer 2
    k_gemm128<<<gGemm, TB>>>(nullptr, 0, W2, N_NODES);
    k_agg128 <<<gAggH, TB>>>(b2, 1);
    // layer 3
    k_gemm128<<<gGemm, TB>>>(nullptr, 1, W3, N_NODES);
    k_agg128 <<<gAggH, TB>>>(b3, 0);
    // layer 4 (transform first -> 32-wide aggregation, fp32) + log_softmax
    k_gemm32 <<<gGemm, TB>>>(0, W4, N_NODES);
    k_agg32_lsm<<<gAgg, TB>>>(b4, out);
}

// round 13
// speedup vs baseline: 1.4377x; 1.1905x over previous
#include <cuda_runtime.h>
#include <cuda_fp16.h>
#include <mma.h>

using namespace nvcuda;

#define N_NODES 100000
#define E_MAX   3400000
#define F 128
#define SCAN_NBLK ((N_NODES + 1023) / 1024)   // 98

// ---- static device scratch (allocation-free requirement) ----
__device__ __align__(16) __half g_h0[N_NODES * F];    // hidden states, fp16
__device__ __align__(16) __half g_h1[N_NODES * F];
__device__ __align__(16) __half g_xh[N_NODES * F];    // x converted to fp16
__device__ __align__(16) __half g_g16[N_NODES * F];   // fp16 gather payload
__device__ __align__(16) __half g_wh[3 * F * F];      // W1..W3 in fp16
__device__ float  g_g [N_NODES * 32];                 // layer-4 logits (fp32)
__device__ float  g_dinv[N_NODES];
__device__ int    g_cnt[N_NODES];
__device__ int    g_pos[N_NODES];
__device__ int    g_rowptr[N_NODES + 1];
__device__ int    g_col[E_MAX];
__device__ int    g_bsum[128];
__device__ int    g_boff[128];

__device__ __forceinline__ const __half* pickA(int s) {
    return s < 0 ? g_xh : (s == 0 ? g_h0 : g_h1);
}
__device__ __forceinline__ __half* pick(int s) { return s == 0 ? g_h0 : g_h1; }

struct alignas(16) Half8 { __half2 a, b, c, d; };

// ---- packed f32x2 FMA helpers (gemm32) ----
__device__ __forceinline__ void ffma2(unsigned long long& d,
                                      unsigned long long a, unsigned long long b) {
    asm("fma.rn.f32x2 %0, %1, %2, %0;" : "+l"(d) : "l"(a), "l"(b));
}
__device__ __forceinline__ unsigned long long pack2(float x, float y) {
    unsigned long long r;
    asm("mov.b64 %0, {%1, %2};" : "=l"(r) : "f"(x), "f"(y));
    return r;
}
__device__ __forceinline__ void unpack2(unsigned long long v, float& x, float& y) {
    unsigned lo, hi;
    asm("mov.b64 {%0, %1}, %2;" : "=r"(lo), "=r"(hi) : "l"(v));
    x = __uint_as_float(lo); y = __uint_as_float(hi);
}

__device__ __forceinline__ Half8 to_h8(float4 a0, float4 a1) {
    Half8 h;
    h.a = __floats2half2_rn(a0.x, a0.y);
    h.b = __floats2half2_rn(a0.z, a0.w);
    h.c = __floats2half2_rn(a1.x, a1.y);
    h.d = __floats2half2_rn(a1.z, a1.w);
    return h;
}

// ---- cp.async helpers ----
__device__ __forceinline__ unsigned smem_u32(const void* p) {
    return (unsigned)__cvta_generic_to_shared(p);
}
__device__ __forceinline__ void cp16(unsigned dst, const void* src, bool pred) {
    int sz = pred ? 16 : 0;
    asm volatile("cp.async.ca.shared.global [%0], [%1], 16, %2;\n"
                 :: "r"(dst), "l"(src), "r"(sz));
}
#define CP_COMMIT() asm volatile("cp.async.commit_group;\n" ::: "memory")
#define CP_WAIT(N)  asm volatile("cp.async.wait_group %0;\n" :: "n"(N) : "memory")

// ---------------- prep: zero CSR counters, convert x and W1..3 to fp16 -----------

__global__ void k_prep(const float* __restrict__ x,
                       const float* __restrict__ W1,
                       const float* __restrict__ W2,
                       const float* __restrict__ W3) {
    long long i = (long long)blockIdx.x * blockDim.x + threadIdx.x;
    long long base = i * 8;
    if (base < (long long)N_NODES * F) {
        float4 a0 = *(const float4*)&x[base];
        float4 a1 = *(const float4*)&x[base + 4];
        *(Half8*)&g_xh[base] = to_h8(a0, a1);
    }
    if (i < 3 * 2048) {
        int w = (int)(i >> 11);
        int off = ((int)i & 2047) * 8;
        const float* W = (w == 0) ? W1 : (w == 1) ? W2 : W3;
        float4 b0 = *(const float4*)&W[off];
        float4 b1 = *(const float4*)&W[off + 4];
        *(Half8*)&g_wh[w * F * F + off] = to_h8(b0, b1);
    }
    if (i < N_NODES) { g_cnt[i] = 0; g_pos[i] = 0; }
}

// ---------------- CSR construction (edge_index is int32) ----------------

__global__ void k_count(const int* __restrict__ ei, int E) {
    int e = blockIdx.x * blockDim.x + threadIdx.x;
    if (e < E) {
        int d = ei[E + e];
        if ((unsigned)d < N_NODES) atomicAdd(&g_cnt[d], 1);
    }
}

__global__ void k_dinv() {
    int i = blockIdx.x * blockDim.x + threadIdx.x;
    if (i < N_NODES) {
        float deg = (float)(g_cnt[i] + 1);   // +1 self loop
        g_dinv[i] = rsqrtf(deg);
    }
}

__global__ __launch_bounds__(1024) void k_scan1() {
    __shared__ int wsum[32];
    int tid = threadIdx.x, lane = tid & 31, wid = tid >> 5;
    int i = blockIdx.x * 1024 + tid;
    int v = (i < N_NODES) ? g_cnt[i] : 0;
    int x = v;
    #pragma unroll
    for (int off = 1; off < 32; off <<= 1) {
        int t = __shfl_up_sync(0xffffffffu, x, off);
        if (lane >= off) x += t;
    }
    if (lane == 31) wsum[wid] = x;
    __syncthreads();
    if (wid == 0) {
        int w = wsum[lane];
        #pragma unroll
        for (int off = 1; off < 32; off <<= 1) {
            int t = __shfl_up_sync(0xffffffffu, w, off);
            if (lane >= off) w += t;
        }
        wsum[lane] = w;
    }
    __syncthreads();
    int excl = x - v + (wid ? wsum[wid - 1] : 0);
    if (i < N_NODES) g_rowptr[i] = excl;
    if (tid == 0) g_bsum[blockIdx.x] = wsum[31];
}

__global__ __launch_bounds__(128) void k_scan2() {
    __shared__ int s[128];
    int tid = threadIdx.x;
    int v = (tid < SCAN_NBLK) ? g_bsum[tid] : 0;
    s[tid] = v;
    __syncthreads();
    #pragma unroll
    for (int off = 1; off < 128; off <<= 1) {
        int t = (tid >= off) ? s[tid - off] : 0;
        __syncthreads();
        s[tid] += t;
        __syncthreads();
    }
    g_boff[tid] = s[tid] - v;          // exclusive
    if (tid == 127) g_rowptr[N_NODES] = s[127];
}

__global__ __launch_bounds__(1024) void k_scan3() {
    int i = blockIdx.x * 1024 + threadIdx.x;
    if (i < N_NODES) g_rowptr[i] += g_boff[blockIdx.x];
}

__global__ void k_fill(const int* __restrict__ ei, int E) {
    int e = blockIdx.x * blockDim.x + threadIdx.x;
    if (e < E) {
        int s = ei[e];
        int d = ei[E + e];
        if ((unsigned)s < N_NODES && (unsigned)d < N_NODES) {
            int p = atomicAdd(&g_pos[d], 1);
            g_col[g_rowptr[d] + p] = s;
        }
    }
}

// ---------------- GEMM (tensor cores, cp.async double-buffered) -------------------
// All-fp16 inputs. A tile + W tile staged by raw 16B cp.async, 2-stage pipeline.
// Block = 128x128 tile, 8 warps (4x2), warp = 32x64. fp32 accumulate.

__global__ __launch_bounds__(256) void k_gemm128(int srcsel, int widx, int M) {
    const __half* __restrict__ A  = pickA(srcsel);
    const __half* __restrict__ Wh = g_wh + widx * F * F;
    __shared__ __half As[2][128][24];    // ld=24 (48B)
    __shared__ __half Bs[2][16][136];    // ld=136 (272B)
    __shared__ float  Cs[8][16 * 20];    // epilogue staging

    int tid  = threadIdx.x;
    int wid  = tid >> 5;
    int lane = tid & 31;
    int row0 = blockIdx.x * 128;
    int wr = wid >> 1;
    int wc = wid & 1;

    // staging geometry
    int ar = tid >> 1;                 // A row 0..127
    int ac = (tid & 1) * 8;            // 8-half chunk
    int br = tid >> 4;                 // W row 0..15
    int bc = (tid & 15) * 8;
    bool avalid = (row0 + ar) < M;
    const __half* Arow = A + (long long)(row0 + (avalid ? ar : 0)) * F + ac;

    // prologue: issue stages 0 and 1
    #pragma unroll
    for (int s = 0; s < 2; s++) {
        cp16(smem_u32(&As[s][ar][ac]), Arow + s * 16, avalid);
        cp16(smem_u32(&Bs[s][br][bc]), Wh + (s * 16 + br) * F + bc, true);
        CP_COMMIT();
    }

    wmma::fragment<wmma::accumulator, 16, 16, 16, float> c[2][4];
    #pragma unroll
    for (int i = 0; i < 2; i++)
        #pragma unroll
        for (int j = 0; j < 4; j++) wmma::fill_fragment(c[i][j], 0.f);

    #pragma unroll
    for (int kk = 0; kk < 8; kk++) {
        if (kk < 7) { CP_WAIT(1); } else { CP_WAIT(0); }
        __syncthreads();
        int cur = kk & 1;
        wmma::fragment<wmma::matrix_a, 16, 16, 16, __half, wmma::row_major> af[2];
        wmma::fragment<wmma::matrix_b, 16, 16, 16, __half, wmma::row_major> bf[4];
        #pragma unroll
        for (int i = 0; i < 2; i++)
            wmma::load_matrix_sync(af[i], &As[cur][wr * 32 + i * 16][0], 24);
        #pragma unroll
        for (int j = 0; j < 4; j++)
            wmma::load_matrix_sync(bf[j], &Bs[cur][0][wc * 64 + j * 16], 136);
        #pragma unroll
        for (int i = 0; i < 2; i++)
            #pragma unroll
            for (int j = 0; j < 4; j++)
                wmma::mma_sync(c[i][j], af[i], bf[j], c[i][j]);
        __syncthreads();
        if (kk < 6) {
            cp16(smem_u32(&As[cur][ar][ac]), Arow + (kk + 2) * 16, avalid);
            cp16(smem_u32(&Bs[cur][br][bc]), Wh + ((kk + 2) * 16 + br) * F + bc, true);
            CP_COMMIT();
        }
    }

    // epilogue: per 16x16 tile, stage to smem, scale by dinv[row], emit fp16
    #pragma unroll
    for (int i = 0; i < 2; i++) {
        #pragma unroll
        for (int j = 0; j < 4; j++) {
            wmma::store_matrix_sync(&Cs[wid][0], c[i][j], 20, wmma::mem_row_major);
            __syncwarp();
            int rr = lane >> 1;
            int c0 = (lane & 1) * 8;
            int grow = row0 + wr * 32 + i * 16 + rr;
            if (grow < M) {
                float d = g_dinv[grow];
                const float* src = &Cs[wid][rr * 20 + c0];
                Half8 h;
                h.a = __floats2half2_rn(src[0] * d, src[1] * d);
                h.b = __floats2half2_rn(src[2] * d, src[3] * d);
                h.c = __floats2half2_rn(src[4] * d, src[5] * d);
                h.d = __floats2half2_rn(src[6] * d, src[7] * d);
                *(Half8*)&g_g16[(long long)grow * 128 + wc * 64 + j * 16 + c0] = h;
            }
            __syncwarp();
        }
    }
}

// ---------------- GEMM 128x32 (last layer), fp16 A -> fp32 FFMA2 -> g_g [M,32] ----

__global__ __launch_bounds__(256) void k_gemm32(int srcsel,
                                                const float* __restrict__ W, int M) {
    const __half* __restrict__ A = pick(srcsel);
    __shared__ float As[16][128];
    __shared__ float Bs[16][32];
    int tid = threadIdx.x;
    int row0 = blockIdx.x * 128;
    int tr = tid >> 3;
    int tc = tid & 7;
    unsigned long long acc[2][4];
    #pragma unroll
    for (int p = 0; p < 2; p++)
        #pragma unroll
        for (int j = 0; j < 4; j++) acc[p][j] = 0ull;

    for (int k0 = 0; k0 < 128; k0 += 16) {
        #pragma unroll
        for (int it = 0; it < 2; it++) {
            int idx = tid + it * 256;
            int r  = idx >> 2;
            int kc = (idx & 3) * 4;
            int grow = row0 + r;
            float4 a;
            if (grow < M) {
                uint2 hv = *(const uint2*)&A[(long long)grow * 128 + k0 + kc];
                float2 p0 = __half22float2(*(__half2*)&hv.x);
                float2 p1 = __half22float2(*(__half2*)&hv.y);
                a = make_float4(p0.x, p0.y, p1.x, p1.y);
            } else {
                a = make_float4(0.f, 0.f, 0.f, 0.f);
            }
            As[kc + 0][r] = a.x; As[kc + 1][r] = a.y;
            As[kc + 2][r] = a.z; As[kc + 3][r] = a.w;
        }
        if (tid < 128) {
            int r = tid >> 3;
            int c = (tid & 7) * 4;
            *(float4*)&Bs[r][c] = *(const float4*)&W[(k0 + r) * 32 + c];
        }
        __syncthreads();
        #pragma unroll
        for (int k = 0; k < 16; k++) {
            const unsigned long long* ap =
                (const unsigned long long*)&As[k][tr * 4];
            unsigned long long a01 = ap[0], a23 = ap[1];
            float b0[4];
            *(float4*)&b0[0] = *(const float4*)&Bs[k][tc * 4];
            #pragma unroll
            for (int j = 0; j < 4; j++) {
                unsigned long long bb = pack2(b0[j], b0[j]);
                ffma2(acc[0][j], a01, bb);
                ffma2(acc[1][j], a23, bb);
            }
        }
        __syncthreads();
    }
    #pragma unroll
    for (int p = 0; p < 2; p++) {
        float lo[4], hi[4];
        #pragma unroll
        for (int j = 0; j < 4; j++) unpack2(acc[p][j], lo[j], hi[j]);
        int r0 = row0 + tr * 4 + 2 * p;
        if (r0 < M) {
            float d = g_dinv[r0];
            float4 o = make_float4(lo[0] * d, lo[1] * d, lo[2] * d, lo[3] * d);
            *(float4*)&g_g[(long long)r0 * 32 + tc * 4] = o;
        }
        if (r0 + 1 < M) {
            float d = g_dinv[r0 + 1];
            float4 o = make_float4(hi[0] * d, hi[1] * d, hi[2] * d, hi[3] * d);
            *(float4*)&g_g[(long long)(r0 + 1) * 32 + tc * 4] = o;
        }
    }
}

// ---------------- Aggregation (128-wide, fp16, warp per node — R10 best) ----------

__global__ __launch_bounds__(256) void k_agg128(const float* __restrict__ bias,
                                                int dstsel) {
    __shared__ int sidx[8][32];
    __half* __restrict__ out = pick(dstsel);
    int wid = threadIdx.x >> 5, lane = threadIdx.x & 31;
    int gw = blockIdx.x * 8 + wid;
    if (gw >= N_NODES) return;
    const uint2* __restrict__ gg = (const uint2*)g_g16;

    uint2 self = gg[(long long)gw * 32 + lane];
    float2 f0 = __half22float2(*(__half2*)&self.x);
    float2 f1 = __half22float2(*(__half2*)&self.y);
    float4 acc = make_float4(f0.x, f0.y, f1.x, f1.y);

    int s0 = g_rowptr[gw], s1 = g_rowptr[gw + 1];
    for (int base = s0; base < s1; base += 32) {
        int n = min(32, s1 - base);
        sidx[wid][lane] = (base + lane < s1) ? g_col[base + lane] : 0;
        __syncwarp();
        int j = 0;
        for (; j + 8 <= n; j += 8) {
            uint2 v[8];
            #pragma unroll
            for (int t = 0; t < 8; t++) {
                int s = sidx[wid][j + t];
                v[t] = __ldg(&gg[(long long)s * 32 + lane]);
            }
            #pragma unroll
            for (int t = 0; t < 8; t++) {
                float2 a = __half22float2(*(__half2*)&v[t].x);
                float2 b = __half22float2(*(__half2*)&v[t].y);
                acc.x += a.x; acc.y += a.y; acc.z += b.x; acc.w += b.y;
            }
        }
        for (; j < n; j++) {
            int s = sidx[wid][j];
            uint2 v = __ldg(&gg[(long long)s * 32 + lane]);
            float2 a = __half22float2(*(__half2*)&v.x);
            float2 b = __half22float2(*(__half2*)&v.y);
            acc.x += a.x; acc.y += a.y; acc.z += b.x; acc.w += b.y;
        }
        __syncwarp();
    }
    float d = g_dinv[gw];
    float4 b = ((const float4*)bias)[lane];
    float rx = fmaxf(d * acc.x + b.x, 0.f);
    float ry = fmaxf(d * acc.y + b.y, 0.f);
    float rz = fmaxf(d * acc.z + b.z, 0.f);
    float rw = fmaxf(d * acc.w + b.w, 0.f);
    uint2 o;
    *(__half2*)&o.x = __floats2half2_rn(rx, ry);
    *(__half2*)&o.y = __floats2half2_rn(rz, rw);
    ((uint2*)out)[(long long)gw * 32 + lane] = o;
}

// ---------------- Aggregation (32-wide, fp32) + log_softmax fused ----------------

__global__ __launch_bounds__(256) void k_agg32_lsm(const float* __restrict__ bias,
                                                   float* __restrict__ out) {
    __shared__ int sidx[8][32];
    int wid = threadIdx.x >> 5, lane = threadIdx.x & 31;
    int gw = blockIdx.x * 8 + wid;
    if (gw >= N_NODES) return;
    float acc = g_g[(long long)gw * 32 + lane];
    int s0 = g_rowptr[gw], s1 = g_rowptr[gw + 1];
    for (int base = s0; base < s1; base += 32) {
        int n = min(32, s1 - base);
        sidx[wid][lane] = (base + lane < s1) ? g_col[base + lane] : 0;
        __syncwarp();
        int j = 0;
        for (; j + 8 <= n; j += 8) {
            float v[8];
            #pragma unroll
            for (int t = 0; t < 8; t++) {
                int s = sidx[wid][j + t];
                v[t] = __ldg(&g_g[(long long)s * 32 + lane]);
            }
            #pragma unroll
            for (int t = 0; t < 8; t++) acc += v[t];
        }
        for (; j < n; j++) {
            int s = sidx[wid][j];
            acc += __ldg(&g_g[(long long)s * 32 + lane]);
        }
        __syncwarp();
    }
    float v = g_dinv[gw] * acc + bias[lane];
    float mx = v;
    #pragma unroll
    for (int off = 16; off; off >>= 1)
        mx = fmaxf(mx, __shfl_xor_sync(0xffffffffu, mx, off));
    float e = expf(v - mx);
    float sum = e;
    #pragma unroll
    for (int off = 16; off; off >>= 1)
        sum += __shfl_xor_sync(0xffffffffu, sum, off);
    out[(long long)gw * 32 + lane] = v - mx - logf(sum);
}

// ---------------- launch ----------------

extern "C" void kernel_launch(void* const* d_in, const int* in_sizes, int n_in,
                              void* d_out, int out_size) {
    const float* x  = (const float*)d_in[0];
    const int*   ei = (const int*)d_in[1];       // int32
    const float* W1 = (const float*)d_in[2]; const float* b1 = (const float*)d_in[3];
    const float* W2 = (const float*)d_in[4]; const float* b2 = (const float*)d_in[5];
    const float* W3 = (const float*)d_in[6]; const float* b3 = (const float*)d_in[7];
    const float* W4 = (const float*)d_in[8]; const float* b4 = (const float*)d_in[9];
    float* out = (float*)d_out;
    int E = in_sizes[1] / 2;
    if (E > E_MAX) E = E_MAX;

    const int TB = 256;
    int gN = (N_NODES + TB - 1) / TB;
    int gE = (E + TB - 1) / TB;
    int gGemm = (N_NODES + 127) / 128;
    int gAgg  = (N_NODES + 7) / 8;
    int gPrep = ((N_NODES * F / 8) + TB - 1) / TB;   // 6250

    // prep (zero + fp16 conversions) + CSR build; gemm128 is 4th launch (profiled)
    k_prep   <<<gPrep, TB>>>(x, W1, W2, W3);
    k_count  <<<gE, TB>>>(ei, E);
    k_dinv   <<<gN, TB>>>();
    k_gemm128<<<gGemm, TB>>>(-1, 0, N_NODES);       // layer-1 GEMM (x -> g_g16)
    k_scan1  <<<SCAN_NBLK, 1024>>>();
    k_scan2  <<<1, 128>>>();
    k_scan3  <<<SCAN_NBLK, 1024>>>();
    k_fill   <<<gE, TB>>>(ei, E);

    // layer 1 aggregation
    k_agg128 <<<gAgg, TB>>>(b1, 0);
    // layer 2
    k_gemm128<<<gGemm, TB>>>(0, 1, N_NODES);
    k_agg128 <<<gAgg, TB>>>(b2, 1);
    // layer 3
    k_gemm128<<<gGemm, TB>>>(1, 2, N_NODES);
    k_agg128 <<<gAgg, TB>>>(b3, 0);
    // layer 4 (transform first -> 32-wide aggregation, fp32) + log_softmax
    k_gemm32 <<<gGemm, TB>>>(0, W4, N_NODES);
    k_agg32_lsm<<<gAgg, TB>>>(b4, out);
}